// round 12
// baseline (speedup 1.0000x reference)
#include <cuda_runtime.h>
#include <cuda_bf16.h>
#include <cstdint>
#include <cstddef>

#define N_NODES 40000
#define N_EDGES 640000
#define IN_F    256
#define EDGE_F  64
#define OUT_F   128
#define NH      8
#define DH      16
#define GEMM_BLOCKS 313

// ---------------- scratch ----------------
__device__ __align__(16) float g_Wh[(size_t)N_NODES * OUT_F];
__device__ __align__(16) float g_ssrc[N_NODES * NH];
__device__ __align__(16) float g_sdst[N_NODES * NH];
__device__ __align__(16) float g_sval[(size_t)N_EDGES * NH];   // CSR-ordered edge scores
__device__ __align__(16) int   g_ssidx[N_EDGES];               // CSR-ordered src ids
__device__ __align__(16) int   g_count[N_NODES];
__device__ __align__(16) int   g_rowstart[N_NODES + 1];
__device__ __align__(16) int   g_cursor[N_NODES];
__device__ float g_weff[NH * EDGE_F];
__device__ float g_beff[NH];

// ---------------- helpers ----------------
__device__ __forceinline__ uint32_t smem_u32(const void* p) {
    uint32_t a;
    asm("{ .reg .u64 t; cvta.to.shared.u64 t, %1; cvt.u32.u64 %0, t; }" : "=r"(a) : "l"(p));
    return a;
}
__device__ __forceinline__ uint32_t swz(uint32_t off) {
    return off ^ ((off >> 3) & 0x70);
}
__device__ __forceinline__ void ldsm4(uint32_t& r0, uint32_t& r1, uint32_t& r2, uint32_t& r3, uint32_t addr) {
    asm volatile("ldmatrix.sync.aligned.m8n8.x4.shared.b16 {%0,%1,%2,%3}, [%4];"
                 : "=r"(r0), "=r"(r1), "=r"(r2), "=r"(r3) : "r"(addr));
}
__device__ __forceinline__ void mma16816(float* c, uint32_t a0, uint32_t a1, uint32_t a2, uint32_t a3,
                                         uint32_t b0, uint32_t b1) {
    asm volatile("mma.sync.aligned.m16n8k16.row.col.f32.bf16.bf16.f32 "
                 "{%0,%1,%2,%3}, {%4,%5,%6,%7}, {%8,%9}, {%0,%1,%2,%3};"
                 : "+f"(c[0]), "+f"(c[1]), "+f"(c[2]), "+f"(c[3])
                 : "r"(a0), "r"(a1), "r"(a2), "r"(a3), "r"(b0), "r"(b1));
}
__device__ __forceinline__ uint32_t pack_bf16x2(float a, float b) {
    __nv_bfloat16 x = __float2bfloat16(a), y = __float2bfloat16(b);
    return (uint32_t)__bfloat16_as_ushort(x) | ((uint32_t)__bfloat16_as_ushort(y) << 16);
}

// ---------------- K1: bf16-split MMA GEMM + fused s_src/s_dst + fused dst histogram / weff ----------------
#define SMEM_GEMM 65536
__global__ __launch_bounds__(256) void k_gemm(const float* __restrict__ A,
                                              const float* __restrict__ B,
                                              const float* __restrict__ bias,
                                              const float* __restrict__ attn,
                                              const int* __restrict__ dst,
                                              const float* __restrict__ edge_w,
                                              const float* __restrict__ edge_b) {
    extern __shared__ char sm[];
    const uint32_t A_HI = 0, A_LO = 16384, B_HI = 32768, B_LO = 49152;
    uint32_t sbase = smem_u32(sm);

    int tid = threadIdx.x, w = tid >> 5, lane = tid & 31;
    int m0 = blockIdx.x * 128;
    int wm = (w >> 1) * 32, wn = (w & 1) * 64;
    int g = lane >> 2, t = lane & 3;

    // ---- fused weff/beff precompute (block 0 only; cheap, runs before its GEMM work) ----
    if (blockIdx.x == 0) {
        for (int i = tid; i < NH * EDGE_F; i += 256) {
            int h = i >> 6, k = i & 63;
            float s = 0.f;
            #pragma unroll
            for (int d = 0; d < DH; d++)
                s += edge_w[(h * DH + d) * EDGE_F + k] * attn[h * 48 + 32 + d];
            g_weff[i] = s;
        }
        if (tid < NH) {
            float s = 0.f;
            #pragma unroll
            for (int d = 0; d < DH; d++)
                s += edge_b[tid * DH + d] * attn[tid * 48 + 32 + d];
            g_beff[tid] = s;
        }
    }

    float c[2][8][4];
    #pragma unroll
    for (int mt = 0; mt < 2; mt++)
        #pragma unroll
        for (int nt = 0; nt < 8; nt++)
            #pragma unroll
            for (int j = 0; j < 4; j++) c[mt][nt][j] = 0.f;

    #pragma unroll 1
    for (int chunk = 0; chunk < 4; chunk++) {
        int k0 = chunk << 6;
        #pragma unroll
        for (int i = 0; i < 8; i++) {
            int idx = tid + i * 256;
            int r = idx >> 4;
            int cc = (idx & 15) << 2;
            int m = m0 + r;
            float4 va = (m < N_NODES) ? *(const float4*)&A[(size_t)m * IN_F + k0 + cc]
                                      : make_float4(0.f, 0.f, 0.f, 0.f);
            float4 vb = *(const float4*)&B[(size_t)r * IN_F + k0 + cc];
            uint32_t o = swz((uint32_t)(r * 128 + cc * 2));
            {
                float h0 = __bfloat162float(__float2bfloat16(va.x));
                float h1 = __bfloat162float(__float2bfloat16(va.y));
                float h2 = __bfloat162float(__float2bfloat16(va.z));
                float h3 = __bfloat162float(__float2bfloat16(va.w));
                *(uint2*)(sm + A_HI + o) = make_uint2(pack_bf16x2(h0, h1), pack_bf16x2(h2, h3));
                *(uint2*)(sm + A_LO + o) = make_uint2(pack_bf16x2(va.x - h0, va.y - h1),
                                                      pack_bf16x2(va.z - h2, va.w - h3));
            }
            {
                float h0 = __bfloat162float(__float2bfloat16(vb.x));
                float h1 = __bfloat162float(__float2bfloat16(vb.y));
                float h2 = __bfloat162float(__float2bfloat16(vb.z));
                float h3 = __bfloat162float(__float2bfloat16(vb.w));
                *(uint2*)(sm + B_HI + o) = make_uint2(pack_bf16x2(h0, h1), pack_bf16x2(h2, h3));
                *(uint2*)(sm + B_LO + o) = make_uint2(pack_bf16x2(vb.x - h0, vb.y - h1),
                                                      pack_bf16x2(vb.z - h2, vb.w - h3));
            }
        }
        __syncthreads();

        int lr = lane & 15, lc = (lane >> 4) << 3;
        #pragma unroll
        for (int ks = 0; ks < 4; ks++) {
            int kk = (ks << 4) + lc;
            uint32_t ao0 = swz((uint32_t)((wm + lr) * 128 + kk * 2));
            uint32_t ao1 = swz((uint32_t)((wm + 16 + lr) * 128 + kk * 2));
            uint32_t ah[2][4], al[2][4];
            ldsm4(ah[0][0], ah[0][1], ah[0][2], ah[0][3], sbase + A_HI + ao0);
            ldsm4(ah[1][0], ah[1][1], ah[1][2], ah[1][3], sbase + A_HI + ao1);
            ldsm4(al[0][0], al[0][1], al[0][2], al[0][3], sbase + A_LO + ao0);
            ldsm4(al[1][0], al[1][1], al[1][2], al[1][3], sbase + A_LO + ao1);
            #pragma unroll
            for (int np = 0; np < 4; np++) {
                uint32_t bo = swz((uint32_t)((wn + np * 16 + lr) * 128 + kk * 2));
                uint32_t bh[4], bl[4];
                ldsm4(bh[0], bh[1], bh[2], bh[3], sbase + B_HI + bo);
                ldsm4(bl[0], bl[1], bl[2], bl[3], sbase + B_LO + bo);
                #pragma unroll
                for (int mt = 0; mt < 2; mt++) {
                    mma16816(c[mt][np * 2],     ah[mt][0], ah[mt][1], ah[mt][2], ah[mt][3], bh[0], bh[2]);
                    mma16816(c[mt][np * 2],     ah[mt][0], ah[mt][1], ah[mt][2], ah[mt][3], bl[0], bl[2]);
                    mma16816(c[mt][np * 2],     al[mt][0], al[mt][1], al[mt][2], al[mt][3], bh[0], bh[2]);
                    mma16816(c[mt][np * 2 + 1], ah[mt][0], ah[mt][1], ah[mt][2], ah[mt][3], bh[1], bh[3]);
                    mma16816(c[mt][np * 2 + 1], ah[mt][0], ah[mt][1], ah[mt][2], ah[mt][3], bl[1], bl[3]);
                    mma16816(c[mt][np * 2 + 1], al[mt][0], al[mt][1], al[mt][2], al[mt][3], bh[1], bh[3]);
                }
            }
        }
        __syncthreads();
    }

    // ---- epilogue: bias, store Wh, fused s_src/s_dst ----
    float as0[8], as1[8], ad0[8], ad1[8], bb0[8], bb1[8];
    #pragma unroll
    for (int nt = 0; nt < 8; nt++) {
        int col = wn + nt * 8 + t * 2;
        int h = col >> 4, d = col & 15;
        as0[nt] = attn[h * 48 + d];      as1[nt] = attn[h * 48 + d + 1];
        ad0[nt] = attn[h * 48 + 16 + d]; ad1[nt] = attn[h * 48 + 16 + d + 1];
        bb0[nt] = bias[col];             bb1[nt] = bias[col + 1];
    }
    float ps[2][2][4], pd[2][2][4];
    #pragma unroll
    for (int mt = 0; mt < 2; mt++)
        #pragma unroll
        for (int hf = 0; hf < 2; hf++)
            #pragma unroll
            for (int hh = 0; hh < 4; hh++) { ps[mt][hf][hh] = 0.f; pd[mt][hf][hh] = 0.f; }

    #pragma unroll
    for (int mt = 0; mt < 2; mt++) {
        #pragma unroll
        for (int hf = 0; hf < 2; hf++) {
            int m = m0 + wm + mt * 16 + g + hf * 8;
            bool ok = (m < N_NODES);
            #pragma unroll
            for (int nt = 0; nt < 8; nt++) {
                float v0 = c[mt][nt][hf * 2 + 0] + bb0[nt];
                float v1 = c[mt][nt][hf * 2 + 1] + bb1[nt];
                if (ok) {
                    int col = wn + nt * 8 + t * 2;
                    *(float2*)&g_Wh[(size_t)m * OUT_F + col] = make_float2(v0, v1);
                }
                ps[mt][hf][nt >> 1] += v0 * as0[nt] + v1 * as1[nt];
                pd[mt][hf][nt >> 1] += v0 * ad0[nt] + v1 * ad1[nt];
            }
        }
    }
    #pragma unroll
    for (int mt = 0; mt < 2; mt++)
        #pragma unroll
        for (int hf = 0; hf < 2; hf++)
            #pragma unroll
            for (int hh = 0; hh < 4; hh++) {
                float s = ps[mt][hf][hh], d2 = pd[mt][hf][hh];
                s += __shfl_xor_sync(0xffffffffu, s, 1);
                s += __shfl_xor_sync(0xffffffffu, s, 2);
                d2 += __shfl_xor_sync(0xffffffffu, d2, 1);
                d2 += __shfl_xor_sync(0xffffffffu, d2, 2);
                if (t == 0) {
                    int m = m0 + wm + mt * 16 + g + hf * 8;
                    if (m < N_NODES) {
                        int h = (w & 1) * 4 + hh;
                        g_ssrc[m * NH + h] = s;
                        g_sdst[m * NH + h] = d2;
                    }
                }
            }

    // ---- fused dst histogram: 8 edges per thread, coalesced reads, spread atomics ----
    {
        int base = (blockIdx.x * 256 + tid) * 8;
        #pragma unroll
        for (int j = 0; j < 2; j++) {
            int e4 = base + j * 4;
            if (e4 + 3 < N_EDGES) {
                int4 d4 = *(const int4*)&dst[e4];
                atomicAdd(&g_count[d4.x], 1);
                atomicAdd(&g_count[d4.y], 1);
                atomicAdd(&g_count[d4.z], 1);
                atomicAdd(&g_count[d4.w], 1);
            } else {
                for (int e = e4; e < N_EDGES; e++) atomicAdd(&g_count[dst[e]], 1);
            }
        }
    }
}

// ---------------- K2: single-phase exclusive scan ----------------
__global__ __launch_bounds__(1024) void k_scan() {
    __shared__ int wsum[32];
    int tid = threadIdx.x, lane = tid & 31, wid = tid >> 5;
    int base = tid * 40;
    int4 v[10];
    #pragma unroll
    for (int j = 0; j < 10; j++) {
        int o = base + j * 4;
        v[j] = (o < N_NODES) ? *(const int4*)&g_count[o] : make_int4(0, 0, 0, 0);
    }
    int t = 0;
    #pragma unroll
    for (int j = 0; j < 10; j++) t += v[j].x + v[j].y + v[j].z + v[j].w;
    int x = t;
    #pragma unroll
    for (int o = 1; o < 32; o <<= 1) {
        int y = __shfl_up_sync(0xffffffffu, x, o);
        if (lane >= o) x += y;
    }
    if (lane == 31) wsum[wid] = x;
    __syncthreads();
    if (wid == 0) {
        int wv = wsum[lane], xx = wv;
        #pragma unroll
        for (int o = 1; o < 32; o <<= 1) {
            int y = __shfl_up_sync(0xffffffffu, xx, o);
            if (lane >= o) xx += y;
        }
        wsum[lane] = xx - wv;
    }
    __syncthreads();
    int run = (x - t) + wsum[wid];
    #pragma unroll
    for (int j = 0; j < 10; j++) {
        int o = base + j * 4;
        int4 r;
        r.x = run; run += v[j].x;
        r.y = run; run += v[j].y;
        r.z = run; run += v[j].z;
        r.w = run; run += v[j].w;
        if (o < N_NODES) {
            *(int4*)&g_rowstart[o] = r;
            *(int4*)&g_cursor[o]   = r;
        }
    }
    if (tid == 1023) g_rowstart[N_NODES] = run;
}

// ---------------- K3: s_e via tensor-core MMA (256-edge tile) + CSR scatter ----------------
// dynamic smem layout: A_hi[256x128B] | A_lo[256x128B] | B_hi[8x128B] | B_lo[8x128B] | out[256x8 f32]
#define SE_A_HI 0u
#define SE_A_LO 32768u
#define SE_B_HI 65536u
#define SE_B_LO 66560u
#define SE_OUT  67584u
#define SMEM_SE (67584 + 256 * 8 * 4)
__global__ __launch_bounds__(256) void k_se(const float* __restrict__ EF,
                                            const int* __restrict__ src,
                                            const int* __restrict__ dst) {
    extern __shared__ char sms[];
    __shared__ float sb[NH];
    uint32_t sbase = smem_u32(sms);
    float* sOut = (float*)(sms + SE_OUT);

    int tid = threadIdx.x, w = tid >> 5, lane = tid & 31;
    int e0 = blockIdx.x * 256;

    // stage EF tile: 256 rows x 64 fp32 = 4096 float4 / 256 threads = 16 each (deep MLP)
    #pragma unroll
    for (int i = 0; i < 16; i++) {
        int idx = tid + i * 256;               // 0..4095
        int r = idx >> 4;                      // edge row 0..255
        int cc = (idx & 15) << 2;              // k 0..60
        float4 v = *(const float4*)&EF[(size_t)(e0 + r) * EDGE_F + cc];
        uint32_t o = swz((uint32_t)(r * 128 + cc * 2));
        float h0 = __bfloat162float(__float2bfloat16(v.x));
        float h1 = __bfloat162float(__float2bfloat16(v.y));
        float h2 = __bfloat162float(__float2bfloat16(v.z));
        float h3 = __bfloat162float(__float2bfloat16(v.w));
        *(uint2*)(sms + SE_A_HI + o) = make_uint2(pack_bf16x2(h0, h1), pack_bf16x2(h2, h3));
        *(uint2*)(sms + SE_A_LO + o) = make_uint2(pack_bf16x2(v.x - h0, v.y - h1),
                                                  pack_bf16x2(v.z - h2, v.w - h3));
    }
    // stage w_eff (8x64) hi/lo
    if (tid < 128) {
        int h = tid >> 4, kq = (tid & 15) << 2;
        float4 v = *(const float4*)&g_weff[h * EDGE_F + kq];
        uint32_t o = swz((uint32_t)(h * 128 + kq * 2));
        float h0 = __bfloat162float(__float2bfloat16(v.x));
        float h1 = __bfloat162float(__float2bfloat16(v.y));
        float h2 = __bfloat162float(__float2bfloat16(v.z));
        float h3 = __bfloat162float(__float2bfloat16(v.w));
        *(uint2*)(sms + SE_B_HI + o) = make_uint2(pack_bf16x2(h0, h1), pack_bf16x2(h2, h3));
        *(uint2*)(sms + SE_B_LO + o) = make_uint2(pack_bf16x2(v.x - h0, v.y - h1),
                                                  pack_bf16x2(v.z - h2, v.w - h3));
    }
    if (tid < NH) sb[tid] = g_beff[tid];
    __syncthreads();

    // MMA: each warp owns 32 edges (two 16-row tiles), all 8 heads
    {
        int lr = lane & 15, lc = (lane >> 4) << 3;
        int br = lane & 7;
        float c0[4] = {0.f, 0.f, 0.f, 0.f};
        float c1[4] = {0.f, 0.f, 0.f, 0.f};
        #pragma unroll
        for (int kc = 0; kc < 4; kc++) {
            int kk = (kc << 4) + lc;
            uint32_t ao0 = swz((uint32_t)((w * 32 + lr) * 128 + kk * 2));
            uint32_t ao1 = swz((uint32_t)((w * 32 + 16 + lr) * 128 + kk * 2));
            uint32_t bo = swz((uint32_t)(br * 128 + kk * 2));
            uint32_t ah0[4], al0[4], ah1[4], al1[4], bh[4], bl[4];
            ldsm4(ah0[0], ah0[1], ah0[2], ah0[3], sbase + SE_A_HI + ao0);
            ldsm4(ah1[0], ah1[1], ah1[2], ah1[3], sbase + SE_A_HI + ao1);
            ldsm4(al0[0], al0[1], al0[2], al0[3], sbase + SE_A_LO + ao0);
            ldsm4(al1[0], al1[1], al1[2], al1[3], sbase + SE_A_LO + ao1);
            ldsm4(bh[0], bh[1], bh[2], bh[3], sbase + SE_B_HI + bo);
            ldsm4(bl[0], bl[1], bl[2], bl[3], sbase + SE_B_LO + bo);
            mma16816(c0, ah0[0], ah0[1], ah0[2], ah0[3], bh[0], bh[2]);
            mma16816(c0, ah0[0], ah0[1], ah0[2], ah0[3], bl[0], bl[2]);
            mma16816(c0, al0[0], al0[1], al0[2], al0[3], bh[0], bh[2]);
            mma16816(c1, ah1[0], ah1[1], ah1[2], ah1[3], bh[0], bh[2]);
            mma16816(c1, ah1[0], ah1[1], ah1[2], ah1[3], bl[0], bl[2]);
            mma16816(c1, al1[0], al1[1], al1[2], al1[3], bh[0], bh[2]);
        }
        int g = lane >> 2, t = lane & 3;
        *(float2*)&sOut[(w * 32 + g) * 8 + t * 2]      = make_float2(c0[0], c0[1]);
        *(float2*)&sOut[(w * 32 + g + 8) * 8 + t * 2]  = make_float2(c0[2], c0[3]);
        *(float2*)&sOut[(w * 32 + 16 + g) * 8 + t * 2] = make_float2(c1[0], c1[1]);
        *(float2*)&sOut[(w * 32 + 24 + g) * 8 + t * 2] = make_float2(c1[2], c1[3]);
    }
    __syncthreads();

    // scatter: one thread per edge (all 256 threads)
    {
        int e = e0 + tid;
        int s = src[e], d = dst[e];
        float4 o0 = *(float4*)&sOut[tid * 8];
        float4 o1 = *(float4*)&sOut[tid * 8 + 4];
        float4 r0 = *(const float4*)&g_ssrc[s * NH];
        float4 r1 = *(const float4*)&g_ssrc[s * NH + 4];
        int pos = atomicAdd(&g_cursor[d], 1);
        *(float4*)&g_sval[(size_t)pos * NH] =
            make_float4(o0.x + sb[0] + r0.x, o0.y + sb[1] + r0.y,
                        o0.z + sb[2] + r0.z, o0.w + sb[3] + r0.w);
        *(float4*)&g_sval[(size_t)pos * NH + 4] =
            make_float4(o1.x + sb[4] + r1.x, o1.y + sb[5] + r1.y,
                        o1.z + sb[6] + r1.z, o1.w + sb[7] + r1.w);
        g_ssidx[pos] = s;
    }
}

// ---------------- K4: gather per node (warp/node), unrolled x4 ----------------
__global__ __launch_bounds__(256) void k_gather(float* __restrict__ out) {
    int warp = (blockIdx.x * blockDim.x + threadIdx.x) >> 5;
    int lane = threadIdx.x & 31;
    if (warp >= N_NODES) return;
    int h = lane >> 2;
    float sd = g_sdst[warp * NH + h];
    int beg = g_rowstart[warp], end = g_rowstart[warp + 1];
    float4 acc = make_float4(0.f, 0.f, 0.f, 0.f);
    float z = 0.f;
    int i = beg;
    for (; i + 4 <= end; i += 4) {
        int s0 = g_ssidx[i],     s1 = g_ssidx[i + 1];
        int s2 = g_ssidx[i + 2], s3 = g_ssidx[i + 3];
        float a0 = g_sval[(size_t)i * NH + h];
        float a1 = g_sval[(size_t)(i + 1) * NH + h];
        float a2 = g_sval[(size_t)(i + 2) * NH + h];
        float a3 = g_sval[(size_t)(i + 3) * NH + h];
        float4 w0 = *(const float4*)&g_Wh[(size_t)s0 * OUT_F + lane * 4];
        float4 w1 = *(const float4*)&g_Wh[(size_t)s1 * OUT_F + lane * 4];
        float4 w2 = *(const float4*)&g_Wh[(size_t)s2 * OUT_F + lane * 4];
        float4 w3 = *(const float4*)&g_Wh[(size_t)s3 * OUT_F + lane * 4];
        float e0 = a0 + sd; e0 = fmaxf(e0, 0.2f * e0);
        float e1 = a1 + sd; e1 = fmaxf(e1, 0.2f * e1);
        float e2 = a2 + sd; e2 = fmaxf(e2, 0.2f * e2);
        float e3 = a3 + sd; e3 = fmaxf(e3, 0.2f * e3);
        float x0 = __expf(e0), x1 = __expf(e1), x2 = __expf(e2), x3 = __expf(e3);
        z += (x0 + x1) + (x2 + x3);
        acc.x += x0 * w0.x + x1 * w1.x + x2 * w2.x + x3 * w3.x;
        acc.y += x0 * w0.y + x1 * w1.y + x2 * w2.y + x3 * w3.y;
        acc.z += x0 * w0.z + x1 * w1.z + x2 * w2.z + x3 * w3.z;
        acc.w += x0 * w0.w + x1 * w1.w + x2 * w2.w + x3 * w3.w;
    }
    for (; i < end; i++) {
        int s0 = g_ssidx[i];
        float a0 = g_sval[(size_t)i * NH + h];
        float4 w0 = *(const float4*)&g_Wh[(size_t)s0 * OUT_F + lane * 4];
        float e0 = a0 + sd; e0 = fmaxf(e0, 0.2f * e0);
        float x0 = __expf(e0);
        z += x0;
        acc.x += x0 * w0.x; acc.y += x0 * w0.y;
        acc.z += x0 * w0.z; acc.w += x0 * w0.w;
    }
    float4 o = make_float4(0.f, 0.f, 0.f, 0.f);
    if (end > beg) {
        float inv = 1.f / z;
        o = make_float4(acc.x * inv, acc.y * inv, acc.z * inv, acc.w * inv);
    }
    *(float4*)&out[(size_t)warp * OUT_F + lane * 4] = o;
}

// ---------------- launch ----------------
extern "C" void kernel_launch(void* const* d_in, const int* in_sizes, int n_in,
                              void* d_out, int out_size) {
    const float* node_feats = (const float*)d_in[0];
    const float* edge_feats = (const float*)d_in[1];
    const int*   src        = (const int*)d_in[2];
    const int*   dst        = (const int*)d_in[3];
    const float* node_w     = (const float*)d_in[4];
    const float* node_b     = (const float*)d_in[5];
    const float* edge_w     = (const float*)d_in[6];
    const float* edge_b     = (const float*)d_in[7];
    const float* attn       = (const float*)d_in[8];
    float* out = (float*)d_out;

    void* count_ptr = nullptr;
    cudaGetSymbolAddress(&count_ptr, g_count);
    cudaMemsetAsync(count_ptr, 0, N_NODES * sizeof(int));

    cudaFuncSetAttribute(k_gemm, cudaFuncAttributeMaxDynamicSharedMemorySize, SMEM_GEMM);
    cudaFuncSetAttribute(k_se, cudaFuncAttributeMaxDynamicSharedMemorySize, SMEM_SE);

    k_gemm<<<GEMM_BLOCKS, 256, SMEM_GEMM>>>(node_feats, node_w, node_b, attn,
                                            dst, edge_w, edge_b);
    k_scan<<<1, 1024>>>();
    k_se<<<N_EDGES / 256, 256, SMEM_SE>>>(edge_feats, src, dst);
    k_gather<<<(N_NODES * 32 + 255) / 256, 256>>>(out);
}

// round 13
// speedup vs baseline: 1.0079x; 1.0079x over previous
#include <cuda_runtime.h>
#include <cuda_bf16.h>
#include <cstdint>
#include <cstddef>

#define N_NODES 40000
#define N_EDGES 640000
#define IN_F    256
#define EDGE_F  64
#define OUT_F   128
#define NH      8
#define DH      16
#define GEMM_BLOCKS 313

// ---------------- scratch ----------------
__device__ __align__(16) float g_Wh[(size_t)N_NODES * OUT_F];
__device__ __align__(16) float g_ssrc[N_NODES * NH];
__device__ __align__(16) float g_sdst[N_NODES * NH];
__device__ __align__(16) float g_sval[(size_t)N_EDGES * NH];   // CSR-ordered edge scores
__device__ __align__(16) int   g_ssidx[N_EDGES];               // CSR-ordered src ids
__device__ __align__(16) int   g_count[N_NODES];
__device__ __align__(16) int   g_rowstart[N_NODES + 1];
__device__ __align__(16) int   g_cursor[N_NODES];
__device__ float g_weff[NH * EDGE_F];
__device__ float g_beff[NH];

// ---------------- helpers ----------------
__device__ __forceinline__ uint32_t smem_u32(const void* p) {
    uint32_t a;
    asm("{ .reg .u64 t; cvta.to.shared.u64 t, %1; cvt.u32.u64 %0, t; }" : "=r"(a) : "l"(p));
    return a;
}
__device__ __forceinline__ uint32_t swz(uint32_t off) {
    return off ^ ((off >> 3) & 0x70);
}
__device__ __forceinline__ void ldsm4(uint32_t& r0, uint32_t& r1, uint32_t& r2, uint32_t& r3, uint32_t addr) {
    asm volatile("ldmatrix.sync.aligned.m8n8.x4.shared.b16 {%0,%1,%2,%3}, [%4];"
                 : "=r"(r0), "=r"(r1), "=r"(r2), "=r"(r3) : "r"(addr));
}
__device__ __forceinline__ void mma16816(float* c, uint32_t a0, uint32_t a1, uint32_t a2, uint32_t a3,
                                         uint32_t b0, uint32_t b1) {
    asm volatile("mma.sync.aligned.m16n8k16.row.col.f32.bf16.bf16.f32 "
                 "{%0,%1,%2,%3}, {%4,%5,%6,%7}, {%8,%9}, {%0,%1,%2,%3};"
                 : "+f"(c[0]), "+f"(c[1]), "+f"(c[2]), "+f"(c[3])
                 : "r"(a0), "r"(a1), "r"(a2), "r"(a3), "r"(b0), "r"(b1));
}
__device__ __forceinline__ uint32_t pack_bf16x2(float a, float b) {
    __nv_bfloat16 x = __float2bfloat16(a), y = __float2bfloat16(b);
    return (uint32_t)__bfloat16_as_ushort(x) | ((uint32_t)__bfloat16_as_ushort(y) << 16);
}

// ---------------- K0: dst histogram + fold attn into edge_w (full-chip, R10-proven) ----------------
__global__ void k_init(const int* __restrict__ dst,
                       const float* __restrict__ edge_w,
                       const float* __restrict__ edge_b,
                       const float* __restrict__ attn) {
    int e = blockIdx.x * blockDim.x + threadIdx.x;
    if (e < N_EDGES) atomicAdd(&g_count[dst[e]], 1);
    if (blockIdx.x == 0) {
        for (int i = threadIdx.x; i < NH * EDGE_F; i += blockDim.x) {
            int h = i >> 6, k = i & 63;
            float s = 0.f;
            #pragma unroll
            for (int d = 0; d < DH; d++)
                s += edge_w[(h * DH + d) * EDGE_F + k] * attn[h * 48 + 32 + d];
            g_weff[i] = s;
        }
        if (threadIdx.x < NH) {
            float s = 0.f;
            #pragma unroll
            for (int d = 0; d < DH; d++)
                s += edge_b[threadIdx.x * DH + d] * attn[threadIdx.x * 48 + 32 + d];
            g_beff[threadIdx.x] = s;
        }
    }
}

// ---------------- K1: bf16-split MMA GEMM, register-prefetch pipelined ----------------
#define SMEM_GEMM 65536
__global__ __launch_bounds__(256) void k_gemm(const float* __restrict__ A,
                                              const float* __restrict__ B,
                                              const float* __restrict__ bias,
                                              const float* __restrict__ attn) {
    extern __shared__ char sm[];
    const uint32_t A_HI = 0, A_LO = 16384, B_HI = 32768, B_LO = 49152;
    uint32_t sbase = smem_u32(sm);

    int tid = threadIdx.x, w = tid >> 5, lane = tid & 31;
    int m0 = blockIdx.x * 128;
    int wm = (w >> 1) * 32, wn = (w & 1) * 64;
    int g = lane >> 2, t = lane & 3;

    // per-thread staging coordinates (fixed across chunks)
    int st_r[8], st_c[8];
    bool st_ok[8];
    #pragma unroll
    for (int i = 0; i < 8; i++) {
        int idx = tid + i * 256;
        st_r[i] = idx >> 4;
        st_c[i] = (idx & 15) << 2;
        st_ok[i] = (m0 + st_r[i]) < N_NODES;
    }

    float c[2][8][4];
    #pragma unroll
    for (int mt = 0; mt < 2; mt++)
        #pragma unroll
        for (int nt = 0; nt < 8; nt++)
            #pragma unroll
            for (int j = 0; j < 4; j++) c[mt][nt][j] = 0.f;

    float4 va[8], vb[8];
    // prefetch chunk 0
    #pragma unroll
    for (int i = 0; i < 8; i++) {
        va[i] = st_ok[i] ? *(const float4*)&A[(size_t)(m0 + st_r[i]) * IN_F + st_c[i]]
                         : make_float4(0.f, 0.f, 0.f, 0.f);
        vb[i] = *(const float4*)&B[(size_t)st_r[i] * IN_F + st_c[i]];
    }

    #pragma unroll 1
    for (int chunk = 0; chunk < 4; chunk++) {
        // convert + store staged registers to smem
        #pragma unroll
        for (int i = 0; i < 8; i++) {
            uint32_t o = swz((uint32_t)(st_r[i] * 128 + st_c[i] * 2));
            float4 vA = va[i], vB = vb[i];
            {
                float h0 = __bfloat162float(__float2bfloat16(vA.x));
                float h1 = __bfloat162float(__float2bfloat16(vA.y));
                float h2 = __bfloat162float(__float2bfloat16(vA.z));
                float h3 = __bfloat162float(__float2bfloat16(vA.w));
                *(uint2*)(sm + A_HI + o) = make_uint2(pack_bf16x2(h0, h1), pack_bf16x2(h2, h3));
                *(uint2*)(sm + A_LO + o) = make_uint2(pack_bf16x2(vA.x - h0, vA.y - h1),
                                                      pack_bf16x2(vA.z - h2, vA.w - h3));
            }
            {
                float h0 = __bfloat162float(__float2bfloat16(vB.x));
                float h1 = __bfloat162float(__float2bfloat16(vB.y));
                float h2 = __bfloat162float(__float2bfloat16(vB.z));
                float h3 = __bfloat162float(__float2bfloat16(vB.w));
                *(uint2*)(sm + B_HI + o) = make_uint2(pack_bf16x2(h0, h1), pack_bf16x2(h2, h3));
                *(uint2*)(sm + B_LO + o) = make_uint2(pack_bf16x2(vB.x - h0, vB.y - h1),
                                                      pack_bf16x2(vB.z - h2, vB.w - h3));
            }
        }
        __syncthreads();

        // prefetch next chunk while MMAs run (LDG latency hidden under tensor work)
        if (chunk < 3) {
            int k0n = (chunk + 1) << 6;
            #pragma unroll
            for (int i = 0; i < 8; i++) {
                va[i] = st_ok[i] ? *(const float4*)&A[(size_t)(m0 + st_r[i]) * IN_F + k0n + st_c[i]]
                                 : make_float4(0.f, 0.f, 0.f, 0.f);
                vb[i] = *(const float4*)&B[(size_t)st_r[i] * IN_F + k0n + st_c[i]];
            }
        }

        int lr = lane & 15, lc = (lane >> 4) << 3;
        #pragma unroll
        for (int ks = 0; ks < 4; ks++) {
            int kk = (ks << 4) + lc;
            uint32_t ao0 = swz((uint32_t)((wm + lr) * 128 + kk * 2));
            uint32_t ao1 = swz((uint32_t)((wm + 16 + lr) * 128 + kk * 2));
            uint32_t ah[2][4], al[2][4];
            ldsm4(ah[0][0], ah[0][1], ah[0][2], ah[0][3], sbase + A_HI + ao0);
            ldsm4(ah[1][0], ah[1][1], ah[1][2], ah[1][3], sbase + A_HI + ao1);
            ldsm4(al[0][0], al[0][1], al[0][2], al[0][3], sbase + A_LO + ao0);
            ldsm4(al[1][0], al[1][1], al[1][2], al[1][3], sbase + A_LO + ao1);
            #pragma unroll
            for (int np = 0; np < 4; np++) {
                uint32_t bo = swz((uint32_t)((wn + np * 16 + lr) * 128 + kk * 2));
                uint32_t bh[4], bl[4];
                ldsm4(bh[0], bh[1], bh[2], bh[3], sbase + B_HI + bo);
                ldsm4(bl[0], bl[1], bl[2], bl[3], sbase + B_LO + bo);
                #pragma unroll
                for (int mt = 0; mt < 2; mt++) {
                    mma16816(c[mt][np * 2],     ah[mt][0], ah[mt][1], ah[mt][2], ah[mt][3], bh[0], bh[2]);
                    mma16816(c[mt][np * 2],     ah[mt][0], ah[mt][1], ah[mt][2], ah[mt][3], bl[0], bl[2]);
                    mma16816(c[mt][np * 2],     al[mt][0], al[mt][1], al[mt][2], al[mt][3], bh[0], bh[2]);
                    mma16816(c[mt][np * 2 + 1], ah[mt][0], ah[mt][1], ah[mt][2], ah[mt][3], bh[1], bh[3]);
                    mma16816(c[mt][np * 2 + 1], ah[mt][0], ah[mt][1], ah[mt][2], ah[mt][3], bl[1], bl[3]);
                    mma16816(c[mt][np * 2 + 1], al[mt][0], al[mt][1], al[mt][2], al[mt][3], bh[1], bh[3]);
                }
            }
        }
        __syncthreads();
    }

    // ---- epilogue: bias, store Wh, fused s_src/s_dst ----
    float as0[8], as1[8], ad0[8], ad1[8], bb0[8], bb1[8];
    #pragma unroll
    for (int nt = 0; nt < 8; nt++) {
        int col = wn + nt * 8 + t * 2;
        int h = col >> 4, d = col & 15;
        as0[nt] = attn[h * 48 + d];      as1[nt] = attn[h * 48 + d + 1];
        ad0[nt] = attn[h * 48 + 16 + d]; ad1[nt] = attn[h * 48 + 16 + d + 1];
        bb0[nt] = bias[col];             bb1[nt] = bias[col + 1];
    }
    float ps[2][2][4], pd[2][2][4];
    #pragma unroll
    for (int mt = 0; mt < 2; mt++)
        #pragma unroll
        for (int hf = 0; hf < 2; hf++)
            #pragma unroll
            for (int hh = 0; hh < 4; hh++) { ps[mt][hf][hh] = 0.f; pd[mt][hf][hh] = 0.f; }

    #pragma unroll
    for (int mt = 0; mt < 2; mt++) {
        #pragma unroll
        for (int hf = 0; hf < 2; hf++) {
            int m = m0 + wm + mt * 16 + g + hf * 8;
            bool ok = (m < N_NODES);
            #pragma unroll
            for (int nt = 0; nt < 8; nt++) {
                float v0 = c[mt][nt][hf * 2 + 0] + bb0[nt];
                float v1 = c[mt][nt][hf * 2 + 1] + bb1[nt];
                if (ok) {
                    int col = wn + nt * 8 + t * 2;
                    *(float2*)&g_Wh[(size_t)m * OUT_F + col] = make_float2(v0, v1);
                }
                ps[mt][hf][nt >> 1] += v0 * as0[nt] + v1 * as1[nt];
                pd[mt][hf][nt >> 1] += v0 * ad0[nt] + v1 * ad1[nt];
            }
        }
    }
    #pragma unroll
    for (int mt = 0; mt < 2; mt++)
        #pragma unroll
        for (int hf = 0; hf < 2; hf++)
            #pragma unroll
            for (int hh = 0; hh < 4; hh++) {
                float s = ps[mt][hf][hh], d2 = pd[mt][hf][hh];
                s += __shfl_xor_sync(0xffffffffu, s, 1);
                s += __shfl_xor_sync(0xffffffffu, s, 2);
                d2 += __shfl_xor_sync(0xffffffffu, d2, 1);
                d2 += __shfl_xor_sync(0xffffffffu, d2, 2);
                if (t == 0) {
                    int m = m0 + wm + mt * 16 + g + hf * 8;
                    if (m < N_NODES) {
                        int h = (w & 1) * 4 + hh;
                        g_ssrc[m * NH + h] = s;
                        g_sdst[m * NH + h] = d2;
                    }
                }
            }
}

// ---------------- K2: single-phase exclusive scan ----------------
__global__ __launch_bounds__(1024) void k_scan() {
    __shared__ int wsum[32];
    int tid = threadIdx.x, lane = tid & 31, wid = tid >> 5;
    int base = tid * 40;
    int4 v[10];
    #pragma unroll
    for (int j = 0; j < 10; j++) {
        int o = base + j * 4;
        v[j] = (o < N_NODES) ? *(const int4*)&g_count[o] : make_int4(0, 0, 0, 0);
    }
    int t = 0;
    #pragma unroll
    for (int j = 0; j < 10; j++) t += v[j].x + v[j].y + v[j].z + v[j].w;
    int x = t;
    #pragma unroll
    for (int o = 1; o < 32; o <<= 1) {
        int y = __shfl_up_sync(0xffffffffu, x, o);
        if (lane >= o) x += y;
    }
    if (lane == 31) wsum[wid] = x;
    __syncthreads();
    if (wid == 0) {
        int wv = wsum[lane], xx = wv;
        #pragma unroll
        for (int o = 1; o < 32; o <<= 1) {
            int y = __shfl_up_sync(0xffffffffu, xx, o);
            if (lane >= o) xx += y;
        }
        wsum[lane] = xx - wv;
    }
    __syncthreads();
    int run = (x - t) + wsum[wid];
    #pragma unroll
    for (int j = 0; j < 10; j++) {
        int o = base + j * 4;
        int4 r;
        r.x = run; run += v[j].x;
        r.y = run; run += v[j].y;
        r.z = run; run += v[j].z;
        r.w = run; run += v[j].w;
        if (o < N_NODES) {
            *(int4*)&g_rowstart[o] = r;
            *(int4*)&g_cursor[o]   = r;
        }
    }
    if (tid == 1023) g_rowstart[N_NODES] = run;
}

// ---------------- K3: s_e via tensor-core MMA (256-edge tile) + CSR scatter ----------------
#define SE_A_HI 0u
#define SE_A_LO 32768u
#define SE_B_HI 65536u
#define SE_B_LO 66560u
#define SE_OUT  67584u
#define SMEM_SE (67584 + 256 * 8 * 4)
__global__ __launch_bounds__(256) void k_se(const float* __restrict__ EF,
                                            const int* __restrict__ src,
                                            const int* __restrict__ dst) {
    extern __shared__ char sms[];
    __shared__ float sb[NH];
    uint32_t sbase = smem_u32(sms);
    float* sOut = (float*)(sms + SE_OUT);

    int tid = threadIdx.x, w = tid >> 5, lane = tid & 31;
    int e0 = blockIdx.x * 256;

    #pragma unroll
    for (int i = 0; i < 16; i++) {
        int idx = tid + i * 256;
        int r = idx >> 4;
        int cc = (idx & 15) << 2;
        float4 v = *(const float4*)&EF[(size_t)(e0 + r) * EDGE_F + cc];
        uint32_t o = swz((uint32_t)(r * 128 + cc * 2));
        float h0 = __bfloat162float(__float2bfloat16(v.x));
        float h1 = __bfloat162float(__float2bfloat16(v.y));
        float h2 = __bfloat162float(__float2bfloat16(v.z));
        float h3 = __bfloat162float(__float2bfloat16(v.w));
        *(uint2*)(sms + SE_A_HI + o) = make_uint2(pack_bf16x2(h0, h1), pack_bf16x2(h2, h3));
        *(uint2*)(sms + SE_A_LO + o) = make_uint2(pack_bf16x2(v.x - h0, v.y - h1),
                                                  pack_bf16x2(v.z - h2, v.w - h3));
    }
    if (tid < 128) {
        int h = tid >> 4, kq = (tid & 15) << 2;
        float4 v = *(const float4*)&g_weff[h * EDGE_F + kq];
        uint32_t o = swz((uint32_t)(h * 128 + kq * 2));
        float h0 = __bfloat162float(__float2bfloat16(v.x));
        float h1 = __bfloat162float(__float2bfloat16(v.y));
        float h2 = __bfloat162float(__float2bfloat16(v.z));
        float h3 = __bfloat162float(__float2bfloat16(v.w));
        *(uint2*)(sms + SE_B_HI + o) = make_uint2(pack_bf16x2(h0, h1), pack_bf16x2(h2, h3));
        *(uint2*)(sms + SE_B_LO + o) = make_uint2(pack_bf16x2(v.x - h0, v.y - h1),
                                                  pack_bf16x2(v.z - h2, v.w - h3));
    }
    if (tid < NH) sb[tid] = g_beff[tid];
    __syncthreads();

    {
        int lr = lane & 15, lc = (lane >> 4) << 3;
        int br = lane & 7;
        float c0[4] = {0.f, 0.f, 0.f, 0.f};
        float c1[4] = {0.f, 0.f, 0.f, 0.f};
        #pragma unroll
        for (int kc = 0; kc < 4; kc++) {
            int kk = (kc << 4) + lc;
            uint32_t ao0 = swz((uint32_t)((w * 32 + lr) * 128 + kk * 2));
            uint32_t ao1 = swz((uint32_t)((w * 32 + 16 + lr) * 128 + kk * 2));
            uint32_t bo = swz((uint32_t)(br * 128 + kk * 2));
            uint32_t ah0[4], al0[4], ah1[4], al1[4], bh[4], bl[4];
            ldsm4(ah0[0], ah0[1], ah0[2], ah0[3], sbase + SE_A_HI + ao0);
            ldsm4(ah1[0], ah1[1], ah1[2], ah1[3], sbase + SE_A_HI + ao1);
            ldsm4(al0[0], al0[1], al0[2], al0[3], sbase + SE_A_LO + ao0);
            ldsm4(al1[0], al1[1], al1[2], al1[3], sbase + SE_A_LO + ao1);
            ldsm4(bh[0], bh[1], bh[2], bh[3], sbase + SE_B_HI + bo);
            ldsm4(bl[0], bl[1], bl[2], bl[3], sbase + SE_B_LO + bo);
            mma16816(c0, ah0[0], ah0[1], ah0[2], ah0[3], bh[0], bh[2]);
            mma16816(c0, ah0[0], ah0[1], ah0[2], ah0[3], bl[0], bl[2]);
            mma16816(c0, al0[0], al0[1], al0[2], al0[3], bh[0], bh[2]);
            mma16816(c1, ah1[0], ah1[1], ah1[2], ah1[3], bh[0], bh[2]);
            mma16816(c1, ah1[0], ah1[1], ah1[2], ah1[3], bl[0], bl[2]);
            mma16816(c1, al1[0], al1[1], al1[2], al1[3], bh[0], bh[2]);
        }
        int g = lane >> 2, t = lane & 3;
        *(float2*)&sOut[(w * 32 + g) * 8 + t * 2]      = make_float2(c0[0], c0[1]);
        *(float2*)&sOut[(w * 32 + g + 8) * 8 + t * 2]  = make_float2(c0[2], c0[3]);
        *(float2*)&sOut[(w * 32 + 16 + g) * 8 + t * 2] = make_float2(c1[0], c1[1]);
        *(float2*)&sOut[(w * 32 + 24 + g) * 8 + t * 2] = make_float2(c1[2], c1[3]);
    }
    __syncthreads();

    {
        int e = e0 + tid;
        int s = src[e], d = dst[e];
        float4 o0 = *(float4*)&sOut[tid * 8];
        float4 o1 = *(float4*)&sOut[tid * 8 + 4];
        float4 r0 = *(const float4*)&g_ssrc[s * NH];
        float4 r1 = *(const float4*)&g_ssrc[s * NH + 4];
        int pos = atomicAdd(&g_cursor[d], 1);
        *(float4*)&g_sval[(size_t)pos * NH] =
            make_float4(o0.x + sb[0] + r0.x, o0.y + sb[1] + r0.y,
                        o0.z + sb[2] + r0.z, o0.w + sb[3] + r0.w);
        *(float4*)&g_sval[(size_t)pos * NH + 4] =
            make_float4(o1.x + sb[4] + r1.x, o1.y + sb[5] + r1.y,
                        o1.z + sb[6] + r1.z, o1.w + sb[7] + r1.w);
        g_ssidx[pos] = s;
    }
}

// ---------------- K4: gather per node (warp/node), unrolled x4 ----------------
__global__ __launch_bounds__(256) void k_gather(float* __restrict__ out) {
    int warp = (blockIdx.x * blockDim.x + threadIdx.x) >> 5;
    int lane = threadIdx.x & 31;
    if (warp >= N_NODES) return;
    int h = lane >> 2;
    float sd = g_sdst[warp * NH + h];
    int beg = g_rowstart[warp], end = g_rowstart[warp + 1];
    float4 acc = make_float4(0.f, 0.f, 0.f, 0.f);
    float z = 0.f;
    int i = beg;
    for (; i + 4 <= end; i += 4) {
        int s0 = g_ssidx[i],     s1 = g_ssidx[i + 1];
        int s2 = g_ssidx[i + 2], s3 = g_ssidx[i + 3];
        float a0 = g_sval[(size_t)i * NH + h];
        float a1 = g_sval[(size_t)(i + 1) * NH + h];
        float a2 = g_sval[(size_t)(i + 2) * NH + h];
        float a3 = g_sval[(size_t)(i + 3) * NH + h];
        float4 w0 = *(const float4*)&g_Wh[(size_t)s0 * OUT_F + lane * 4];
        float4 w1 = *(const float4*)&g_Wh[(size_t)s1 * OUT_F + lane * 4];
        float4 w2 = *(const float4*)&g_Wh[(size_t)s2 * OUT_F + lane * 4];
        float4 w3 = *(const float4*)&g_Wh[(size_t)s3 * OUT_F + lane * 4];
        float e0 = a0 + sd; e0 = fmaxf(e0, 0.2f * e0);
        float e1 = a1 + sd; e1 = fmaxf(e1, 0.2f * e1);
        float e2 = a2 + sd; e2 = fmaxf(e2, 0.2f * e2);
        float e3 = a3 + sd; e3 = fmaxf(e3, 0.2f * e3);
        float x0 = __expf(e0), x1 = __expf(e1), x2 = __expf(e2), x3 = __expf(e3);
        z += (x0 + x1) + (x2 + x3);
        acc.x += x0 * w0.x + x1 * w1.x + x2 * w2.x + x3 * w3.x;
        acc.y += x0 * w0.y + x1 * w1.y + x2 * w2.y + x3 * w3.y;
        acc.z += x0 * w0.z + x1 * w1.z + x2 * w2.z + x3 * w3.z;
        acc.w += x0 * w0.w + x1 * w1.w + x2 * w2.w + x3 * w3.w;
    }
    for (; i < end; i++) {
        int s0 = g_ssidx[i];
        float a0 = g_sval[(size_t)i * NH + h];
        float4 w0 = *(const float4*)&g_Wh[(size_t)s0 * OUT_F + lane * 4];
        float e0 = a0 + sd; e0 = fmaxf(e0, 0.2f * e0);
        float x0 = __expf(e0);
        z += x0;
        acc.x += x0 * w0.x; acc.y += x0 * w0.y;
        acc.z += x0 * w0.z; acc.w += x0 * w0.w;
    }
    float4 o = make_float4(0.f, 0.f, 0.f, 0.f);
    if (end > beg) {
        float inv = 1.f / z;
        o = make_float4(acc.x * inv, acc.y * inv, acc.z * inv, acc.w * inv);
    }
    *(float4*)&out[(size_t)warp * OUT_F + lane * 4] = o;
}

// ---------------- launch ----------------
extern "C" void kernel_launch(void* const* d_in, const int* in_sizes, int n_in,
                              void* d_out, int out_size) {
    const float* node_feats = (const float*)d_in[0];
    const float* edge_feats = (const float*)d_in[1];
    const int*   src        = (const int*)d_in[2];
    const int*   dst        = (const int*)d_in[3];
    const float* node_w     = (const float*)d_in[4];
    const float* node_b     = (const float*)d_in[5];
    const float* edge_w     = (const float*)d_in[6];
    const float* edge_b     = (const float*)d_in[7];
    const float* attn       = (const float*)d_in[8];
    float* out = (float*)d_out;

    void* count_ptr = nullptr;
    cudaGetSymbolAddress(&count_ptr, g_count);
    cudaMemsetAsync(count_ptr, 0, N_NODES * sizeof(int));

    cudaFuncSetAttribute(k_gemm, cudaFuncAttributeMaxDynamicSharedMemorySize, SMEM_GEMM);
    cudaFuncSetAttribute(k_se, cudaFuncAttributeMaxDynamicSharedMemorySize, SMEM_SE);

    k_init<<<(N_EDGES + 255) / 256, 256>>>(dst, edge_w, edge_b, attn);
    k_gemm<<<GEMM_BLOCKS, 256, SMEM_GEMM>>>(node_feats, node_w, node_b, attn);
    k_scan<<<1, 1024>>>();
    k_se<<<N_EDGES / 256, 256, SMEM_SE>>>(edge_feats, src, dst);
    k_gather<<<(N_NODES * 32 + 255) / 256, 256>>>(out);
}

// round 14
// speedup vs baseline: 1.0092x; 1.0012x over previous
#include <cuda_runtime.h>
#include <cuda_bf16.h>
#include <cstdint>
#include <cstddef>

#define N_NODES 40000
#define N_EDGES 640000
#define IN_F    256
#define EDGE_F  64
#define OUT_F   128
#define NH      8
#define DH      16
#define GEMM_BLOCKS 313

// ---------------- scratch ----------------
__device__ __align__(16) float g_Wh[(size_t)N_NODES * OUT_F];
__device__ __align__(16) float g_ssrc[N_NODES * NH];
__device__ __align__(16) float g_sdst[N_NODES * NH];
__device__ __align__(16) float g_sval[(size_t)N_EDGES * NH];   // CSR-ordered edge scores
__device__ __align__(16) int   g_ssidx[N_EDGES];               // CSR-ordered src ids
__device__ __align__(16) int   g_count[N_NODES];
__device__ __align__(16) int   g_rowstart[N_NODES + 1];
__device__ __align__(16) int   g_cursor[N_NODES];
__device__ float g_weff[NH * EDGE_F];
__device__ float g_beff[NH];

// ---------------- helpers ----------------
__device__ __forceinline__ uint32_t smem_u32(const void* p) {
    uint32_t a;
    asm("{ .reg .u64 t; cvta.to.shared.u64 t, %1; cvt.u32.u64 %0, t; }" : "=r"(a) : "l"(p));
    return a;
}
__device__ __forceinline__ uint32_t swz(uint32_t off) {
    return off ^ ((off >> 3) & 0x70);
}
__device__ __forceinline__ void ldsm4(uint32_t& r0, uint32_t& r1, uint32_t& r2, uint32_t& r3, uint32_t addr) {
    asm volatile("ldmatrix.sync.aligned.m8n8.x4.shared.b16 {%0,%1,%2,%3}, [%4];"
                 : "=r"(r0), "=r"(r1), "=r"(r2), "=r"(r3) : "r"(addr));
}
__device__ __forceinline__ void mma16816(float* c, uint32_t a0, uint32_t a1, uint32_t a2, uint32_t a3,
                                         uint32_t b0, uint32_t b1) {
    asm volatile("mma.sync.aligned.m16n8k16.row.col.f32.bf16.bf16.f32 "
                 "{%0,%1,%2,%3}, {%4,%5,%6,%7}, {%8,%9}, {%0,%1,%2,%3};"
                 : "+f"(c[0]), "+f"(c[1]), "+f"(c[2]), "+f"(c[3])
                 : "r"(a0), "r"(a1), "r"(a2), "r"(a3), "r"(b0), "r"(b1));
}
__device__ __forceinline__ uint32_t pack_bf16x2(float a, float b) {
    __nv_bfloat16 x = __float2bfloat16(a), y = __float2bfloat16(b);
    return (uint32_t)__bfloat16_as_ushort(x) | ((uint32_t)__bfloat16_as_ushort(y) << 16);
}

// ---------------- K0: dst histogram + fold attn into edge_w ----------------
__global__ void k_init(const int* __restrict__ dst,
                       const float* __restrict__ edge_w,
                       const float* __restrict__ edge_b,
                       const float* __restrict__ attn) {
    int e = blockIdx.x * blockDim.x + threadIdx.x;
    if (e < N_EDGES) atomicAdd(&g_count[dst[e]], 1);
    if (blockIdx.x == 0) {
        for (int i = threadIdx.x; i < NH * EDGE_F; i += blockDim.x) {
            int h = i >> 6, k = i & 63;
            float s = 0.f;
            #pragma unroll
            for (int d = 0; d < DH; d++)
                s += edge_w[(h * DH + d) * EDGE_F + k] * attn[h * 48 + 32 + d];
            g_weff[i] = s;
        }
        if (threadIdx.x < NH) {
            float s = 0.f;
            #pragma unroll
            for (int d = 0; d < DH; d++)
                s += edge_b[threadIdx.x * DH + d] * attn[threadIdx.x * 48 + 32 + d];
            g_beff[threadIdx.x] = s;
        }
    }
}

// ---------------- K1: bf16-split MMA GEMM, register-prefetch pipelined (R13-proven) ----------------
#define SMEM_GEMM 65536
__global__ __launch_bounds__(256) void k_gemm(const float* __restrict__ A,
                                              const float* __restrict__ B,
                                              const float* __restrict__ bias,
                                              const float* __restrict__ attn) {
    extern __shared__ char sm[];
    const uint32_t A_HI = 0, A_LO = 16384, B_HI = 32768, B_LO = 49152;
    uint32_t sbase = smem_u32(sm);

    int tid = threadIdx.x, w = tid >> 5, lane = tid & 31;
    int m0 = blockIdx.x * 128;
    int wm = (w >> 1) * 32, wn = (w & 1) * 64;
    int g = lane >> 2, t = lane & 3;

    int st_r[8], st_c[8];
    bool st_ok[8];
    #pragma unroll
    for (int i = 0; i < 8; i++) {
        int idx = tid + i * 256;
        st_r[i] = idx >> 4;
        st_c[i] = (idx & 15) << 2;
        st_ok[i] = (m0 + st_r[i]) < N_NODES;
    }

    float c[2][8][4];
    #pragma unroll
    for (int mt = 0; mt < 2; mt++)
        #pragma unroll
        for (int nt = 0; nt < 8; nt++)
            #pragma unroll
            for (int j = 0; j < 4; j++) c[mt][nt][j] = 0.f;

    float4 va[8], vb[8];
    #pragma unroll
    for (int i = 0; i < 8; i++) {
        va[i] = st_ok[i] ? *(const float4*)&A[(size_t)(m0 + st_r[i]) * IN_F + st_c[i]]
                         : make_float4(0.f, 0.f, 0.f, 0.f);
        vb[i] = *(const float4*)&B[(size_t)st_r[i] * IN_F + st_c[i]];
    }

    #pragma unroll 1
    for (int chunk = 0; chunk < 4; chunk++) {
        #pragma unroll
        for (int i = 0; i < 8; i++) {
            uint32_t o = swz((uint32_t)(st_r[i] * 128 + st_c[i] * 2));
            float4 vA = va[i], vB = vb[i];
            {
                float h0 = __bfloat162float(__float2bfloat16(vA.x));
                float h1 = __bfloat162float(__float2bfloat16(vA.y));
                float h2 = __bfloat162float(__float2bfloat16(vA.z));
                float h3 = __bfloat162float(__float2bfloat16(vA.w));
                *(uint2*)(sm + A_HI + o) = make_uint2(pack_bf16x2(h0, h1), pack_bf16x2(h2, h3));
                *(uint2*)(sm + A_LO + o) = make_uint2(pack_bf16x2(vA.x - h0, vA.y - h1),
                                                      pack_bf16x2(vA.z - h2, vA.w - h3));
            }
            {
                float h0 = __bfloat162float(__float2bfloat16(vB.x));
                float h1 = __bfloat162float(__float2bfloat16(vB.y));
                float h2 = __bfloat162float(__float2bfloat16(vB.z));
                float h3 = __bfloat162float(__float2bfloat16(vB.w));
                *(uint2*)(sm + B_HI + o) = make_uint2(pack_bf16x2(h0, h1), pack_bf16x2(h2, h3));
                *(uint2*)(sm + B_LO + o) = make_uint2(pack_bf16x2(vB.x - h0, vB.y - h1),
                                                      pack_bf16x2(vB.z - h2, vB.w - h3));
            }
        }
        __syncthreads();

        if (chunk < 3) {
            int k0n = (chunk + 1) << 6;
            #pragma unroll
            for (int i = 0; i < 8; i++) {
                va[i] = st_ok[i] ? *(const float4*)&A[(size_t)(m0 + st_r[i]) * IN_F + k0n + st_c[i]]
                                 : make_float4(0.f, 0.f, 0.f, 0.f);
                vb[i] = *(const float4*)&B[(size_t)st_r[i] * IN_F + k0n + st_c[i]];
            }
        }

        int lr = lane & 15, lc = (lane >> 4) << 3;
        #pragma unroll
        for (int ks = 0; ks < 4; ks++) {
            int kk = (ks << 4) + lc;
            uint32_t ao0 = swz((uint32_t)((wm + lr) * 128 + kk * 2));
            uint32_t ao1 = swz((uint32_t)((wm + 16 + lr) * 128 + kk * 2));
            uint32_t ah[2][4], al[2][4];
            ldsm4(ah[0][0], ah[0][1], ah[0][2], ah[0][3], sbase + A_HI + ao0);
            ldsm4(ah[1][0], ah[1][1], ah[1][2], ah[1][3], sbase + A_HI + ao1);
            ldsm4(al[0][0], al[0][1], al[0][2], al[0][3], sbase + A_LO + ao0);
            ldsm4(al[1][0], al[1][1], al[1][2], al[1][3], sbase + A_LO + ao1);
            #pragma unroll
            for (int np = 0; np < 4; np++) {
                uint32_t bo = swz((uint32_t)((wn + np * 16 + lr) * 128 + kk * 2));
                uint32_t bh[4], bl[4];
                ldsm4(bh[0], bh[1], bh[2], bh[3], sbase + B_HI + bo);
                ldsm4(bl[0], bl[1], bl[2], bl[3], sbase + B_LO + bo);
                #pragma unroll
                for (int mt = 0; mt < 2; mt++) {
                    mma16816(c[mt][np * 2],     ah[mt][0], ah[mt][1], ah[mt][2], ah[mt][3], bh[0], bh[2]);
                    mma16816(c[mt][np * 2],     ah[mt][0], ah[mt][1], ah[mt][2], ah[mt][3], bl[0], bl[2]);
                    mma16816(c[mt][np * 2],     al[mt][0], al[mt][1], al[mt][2], al[mt][3], bh[0], bh[2]);
                    mma16816(c[mt][np * 2 + 1], ah[mt][0], ah[mt][1], ah[mt][2], ah[mt][3], bh[1], bh[3]);
                    mma16816(c[mt][np * 2 + 1], ah[mt][0], ah[mt][1], ah[mt][2], ah[mt][3], bl[1], bl[3]);
                    mma16816(c[mt][np * 2 + 1], al[mt][0], al[mt][1], al[mt][2], al[mt][3], bh[1], bh[3]);
                }
            }
        }
        __syncthreads();
    }

    // ---- epilogue ----
    float as0[8], as1[8], ad0[8], ad1[8], bb0[8], bb1[8];
    #pragma unroll
    for (int nt = 0; nt < 8; nt++) {
        int col = wn + nt * 8 + t * 2;
        int h = col >> 4, d = col & 15;
        as0[nt] = attn[h * 48 + d];      as1[nt] = attn[h * 48 + d + 1];
        ad0[nt] = attn[h * 48 + 16 + d]; ad1[nt] = attn[h * 48 + 16 + d + 1];
        bb0[nt] = bias[col];             bb1[nt] = bias[col + 1];
    }
    float ps[2][2][4], pd[2][2][4];
    #pragma unroll
    for (int mt = 0; mt < 2; mt++)
        #pragma unroll
        for (int hf = 0; hf < 2; hf++)
            #pragma unroll
            for (int hh = 0; hh < 4; hh++) { ps[mt][hf][hh] = 0.f; pd[mt][hf][hh] = 0.f; }

    #pragma unroll
    for (int mt = 0; mt < 2; mt++) {
        #pragma unroll
        for (int hf = 0; hf < 2; hf++) {
            int m = m0 + wm + mt * 16 + g + hf * 8;
            bool ok = (m < N_NODES);
            #pragma unroll
            for (int nt = 0; nt < 8; nt++) {
                float v0 = c[mt][nt][hf * 2 + 0] + bb0[nt];
                float v1 = c[mt][nt][hf * 2 + 1] + bb1[nt];
                if (ok) {
                    int col = wn + nt * 8 + t * 2;
                    *(float2*)&g_Wh[(size_t)m * OUT_F + col] = make_float2(v0, v1);
                }
                ps[mt][hf][nt >> 1] += v0 * as0[nt] + v1 * as1[nt];
                pd[mt][hf][nt >> 1] += v0 * ad0[nt] + v1 * ad1[nt];
            }
        }
    }
    #pragma unroll
    for (int mt = 0; mt < 2; mt++)
        #pragma unroll
        for (int hf = 0; hf < 2; hf++)
            #pragma unroll
            for (int hh = 0; hh < 4; hh++) {
                float s = ps[mt][hf][hh], d2 = pd[mt][hf][hh];
                s += __shfl_xor_sync(0xffffffffu, s, 1);
                s += __shfl_xor_sync(0xffffffffu, s, 2);
                d2 += __shfl_xor_sync(0xffffffffu, d2, 1);
                d2 += __shfl_xor_sync(0xffffffffu, d2, 2);
                if (t == 0) {
                    int m = m0 + wm + mt * 16 + g + hf * 8;
                    if (m < N_NODES) {
                        int h = (w & 1) * 4 + hh;
                        g_ssrc[m * NH + h] = s;
                        g_sdst[m * NH + h] = d2;
                    }
                }
            }
}

// ---------------- K2: single-phase exclusive scan ----------------
__global__ __launch_bounds__(1024) void k_scan() {
    __shared__ int wsum[32];
    int tid = threadIdx.x, lane = tid & 31, wid = tid >> 5;
    int base = tid * 40;
    int4 v[10];
    #pragma unroll
    for (int j = 0; j < 10; j++) {
        int o = base + j * 4;
        v[j] = (o < N_NODES) ? *(const int4*)&g_count[o] : make_int4(0, 0, 0, 0);
    }
    int t = 0;
    #pragma unroll
    for (int j = 0; j < 10; j++) t += v[j].x + v[j].y + v[j].z + v[j].w;
    int x = t;
    #pragma unroll
    for (int o = 1; o < 32; o <<= 1) {
        int y = __shfl_up_sync(0xffffffffu, x, o);
        if (lane >= o) x += y;
    }
    if (lane == 31) wsum[wid] = x;
    __syncthreads();
    if (wid == 0) {
        int wv = wsum[lane], xx = wv;
        #pragma unroll
        for (int o = 1; o < 32; o <<= 1) {
            int y = __shfl_up_sync(0xffffffffu, xx, o);
            if (lane >= o) xx += y;
        }
        wsum[lane] = xx - wv;
    }
    __syncthreads();
    int run = (x - t) + wsum[wid];
    #pragma unroll
    for (int j = 0; j < 10; j++) {
        int o = base + j * 4;
        int4 r;
        r.x = run; run += v[j].x;
        r.y = run; run += v[j].y;
        r.z = run; run += v[j].z;
        r.w = run; run += v[j].w;
        if (o < N_NODES) {
            *(int4*)&g_rowstart[o] = r;
            *(int4*)&g_cursor[o]   = r;
        }
    }
    if (tid == 1023) g_rowstart[N_NODES] = run;
}

// ---------------- K3: s_e via tensor-core MMA (128-edge tile, R10-proven) + full-width scatter ----------------
__global__ __launch_bounds__(256) void k_se(const float* __restrict__ EF,
                                            const int* __restrict__ src,
                                            const int* __restrict__ dst) {
    __shared__ __align__(128) char sA_hi[128 * 128];
    __shared__ __align__(128) char sA_lo[128 * 128];
    __shared__ __align__(128) char sB_hi[8 * 128];
    __shared__ __align__(128) char sB_lo[8 * 128];
    __shared__ float sOut[128 * 8];
    __shared__ int   sPos[128];
    __shared__ float sb[NH];

    int tid = threadIdx.x, w = tid >> 5, lane = tid & 31;
    int e0 = blockIdx.x * 128;

    #pragma unroll
    for (int i = 0; i < 8; i++) {
        int idx = tid + i * 256;
        int r = idx >> 4;
        int cc = (idx & 15) << 2;
        float4 v = *(const float4*)&EF[(size_t)(e0 + r) * EDGE_F + cc];
        uint32_t o = swz((uint32_t)(r * 128 + cc * 2));
        float h0 = __bfloat162float(__float2bfloat16(v.x));
        float h1 = __bfloat162float(__float2bfloat16(v.y));
        float h2 = __bfloat162float(__float2bfloat16(v.z));
        float h3 = __bfloat162float(__float2bfloat16(v.w));
        *(uint2*)(sA_hi + o) = make_uint2(pack_bf16x2(h0, h1), pack_bf16x2(h2, h3));
        *(uint2*)(sA_lo + o) = make_uint2(pack_bf16x2(v.x - h0, v.y - h1),
                                          pack_bf16x2(v.z - h2, v.w - h3));
    }
    if (tid < 128) {
        int h = tid >> 4, kq = (tid & 15) << 2;
        float4 v = *(const float4*)&g_weff[h * EDGE_F + kq];
        uint32_t o = swz((uint32_t)(h * 128 + kq * 2));
        float h0 = __bfloat162float(__float2bfloat16(v.x));
        float h1 = __bfloat162float(__float2bfloat16(v.y));
        float h2 = __bfloat162float(__float2bfloat16(v.z));
        float h3 = __bfloat162float(__float2bfloat16(v.w));
        *(uint2*)(sB_hi + o) = make_uint2(pack_bf16x2(h0, h1), pack_bf16x2(h2, h3));
        *(uint2*)(sB_lo + o) = make_uint2(pack_bf16x2(v.x - h0, v.y - h1),
                                          pack_bf16x2(v.z - h2, v.w - h3));
    }
    if (tid < NH) sb[tid] = g_beff[tid];
    __syncthreads();

    // MMA: each warp owns 16 edges, all 8 heads
    {
        uint32_t a_hi = smem_u32(sA_hi), a_lo = smem_u32(sA_lo);
        uint32_t b_hi = smem_u32(sB_hi), b_lo = smem_u32(sB_lo);
        int lr = lane & 15, lc = (lane >> 4) << 3;
        int br = lane & 7;
        float c[4] = {0.f, 0.f, 0.f, 0.f};
        #pragma unroll
        for (int kc = 0; kc < 4; kc++) {
            int kk = (kc << 4) + lc;
            uint32_t ao = swz((uint32_t)((w * 16 + lr) * 128 + kk * 2));
            uint32_t bo = swz((uint32_t)(br * 128 + kk * 2));
            uint32_t ah[4], al[4], bh[4], bl[4];
            ldsm4(ah[0], ah[1], ah[2], ah[3], a_hi + ao);
            ldsm4(al[0], al[1], al[2], al[3], a_lo + ao);
            ldsm4(bh[0], bh[1], bh[2], bh[3], b_hi + bo);
            ldsm4(bl[0], bl[1], bl[2], bl[3], b_lo + bo);
            mma16816(c, ah[0], ah[1], ah[2], ah[3], bh[0], bh[2]);
            mma16816(c, ah[0], ah[1], ah[2], ah[3], bl[0], bl[2]);
            mma16816(c, al[0], al[1], al[2], al[3], bh[0], bh[2]);
        }
        int g = lane >> 2, t = lane & 3;
        *(float2*)&sOut[(w * 16 + g) * 8 + t * 2]     = make_float2(c[0], c[1]);
        *(float2*)&sOut[(w * 16 + g + 8) * 8 + t * 2] = make_float2(c[2], c[3]);
    }
    __syncthreads();

    // scatter phase 1: tid<128 computes pos + writes low half + idx
    if (tid < 128) {
        int e = e0 + tid;
        int s = src[e], d = dst[e];
        int pos = atomicAdd(&g_cursor[d], 1);
        sPos[tid] = pos;
        float4 o0 = *(float4*)&sOut[tid * 8];
        float4 r0 = *(const float4*)&g_ssrc[s * NH];
        *(float4*)&g_sval[(size_t)pos * NH] =
            make_float4(o0.x + sb[0] + r0.x, o0.y + sb[1] + r0.y,
                        o0.z + sb[2] + r0.z, o0.w + sb[3] + r0.w);
        g_ssidx[pos] = s;
    }
    __syncthreads();
    // scatter phase 2: tid>=128 writes high half
    if (tid >= 128) {
        int et = tid - 128;
        int e = e0 + et;
        int s = src[e];
        int pos = sPos[et];
        float4 o1 = *(float4*)&sOut[et * 8 + 4];
        float4 r1 = *(const float4*)&g_ssrc[s * NH + 4];
        *(float4*)&g_sval[(size_t)pos * NH + 4] =
            make_float4(o1.x + sb[4] + r1.x, o1.y + sb[5] + r1.y,
                        o1.z + sb[6] + r1.z, o1.w + sb[7] + r1.w);
    }
}

// ---------------- K4: gather per node (warp/node), unrolled x4 ----------------
__global__ __launch_bounds__(256) void k_gather(float* __restrict__ out) {
    int warp = (blockIdx.x * blockDim.x + threadIdx.x) >> 5;
    int lane = threadIdx.x & 31;
    if (warp >= N_NODES) return;
    int h = lane >> 2;
    float sd = g_sdst[warp * NH + h];
    int beg = g_rowstart[warp], end = g_rowstart[warp + 1];
    float4 acc = make_float4(0.f, 0.f, 0.f, 0.f);
    float z = 0.f;
    int i = beg;
    for (; i + 4 <= end; i += 4) {
        int s0 = g_ssidx[i],     s1 = g_ssidx[i + 1];
        int s2 = g_ssidx[i + 2], s3 = g_ssidx[i + 3];
        float a0 = g_sval[(size_t)i * NH + h];
        float a1 = g_sval[(size_t)(i + 1) * NH + h];
        float a2 = g_sval[(size_t)(i + 2) * NH + h];
        float a3 = g_sval[(size_t)(i + 3) * NH + h];
        float4 w0 = *(const float4*)&g_Wh[(size_t)s0 * OUT_F + lane * 4];
        float4 w1 = *(const float4*)&g_Wh[(size_t)s1 * OUT_F + lane * 4];
        float4 w2 = *(const float4*)&g_Wh[(size_t)s2 * OUT_F + lane * 4];
        float4 w3 = *(const float4*)&g_Wh[(size_t)s3 * OUT_F + lane * 4];
        float e0 = a0 + sd; e0 = fmaxf(e0, 0.2f * e0);
        float e1 = a1 + sd; e1 = fmaxf(e1, 0.2f * e1);
        float e2 = a2 + sd; e2 = fmaxf(e2, 0.2f * e2);
        float e3 = a3 + sd; e3 = fmaxf(e3, 0.2f * e3);
        float x0 = __expf(e0), x1 = __expf(e1), x2 = __expf(e2), x3 = __expf(e3);
        z += (x0 + x1) + (x2 + x3);
        acc.x += x0 * w0.x + x1 * w1.x + x2 * w2.x + x3 * w3.x;
        acc.y += x0 * w0.y + x1 * w1.y + x2 * w2.y + x3 * w3.y;
        acc.z += x0 * w0.z + x1 * w1.z + x2 * w2.z + x3 * w3.z;
        acc.w += x0 * w0.w + x1 * w1.w + x2 * w2.w + x3 * w3.w;
    }
    for (; i < end; i++) {
        int s0 = g_ssidx[i];
        float a0 = g_sval[(size_t)i * NH + h];
        float4 w0 = *(const float4*)&g_Wh[(size_t)s0 * OUT_F + lane * 4];
        float e0 = a0 + sd; e0 = fmaxf(e0, 0.2f * e0);
        float x0 = __expf(e0);
        z += x0;
        acc.x += x0 * w0.x; acc.y += x0 * w0.y;
        acc.z += x0 * w0.z; acc.w += x0 * w0.w;
    }
    float4 o = make_float4(0.f, 0.f, 0.f, 0.f);
    if (end > beg) {
        float inv = 1.f / z;
        o = make_float4(acc.x * inv, acc.y * inv, acc.z * inv, acc.w * inv);
    }
    *(float4*)&out[(size_t)warp * OUT_F + lane * 4] = o;
}

// ---------------- launch ----------------
extern "C" void kernel_launch(void* const* d_in, const int* in_sizes, int n_in,
                              void* d_out, int out_size) {
    const float* node_feats = (const float*)d_in[0];
    const float* edge_feats = (const float*)d_in[1];
    const int*   src        = (const int*)d_in[2];
    const int*   dst        = (const int*)d_in[3];
    const float* node_w     = (const float*)d_in[4];
    const float* node_b     = (const float*)d_in[5];
    const float* edge_w     = (const float*)d_in[6];
    const float* edge_b     = (const float*)d_in[7];
    const float* attn       = (const float*)d_in[8];
    float* out = (float*)d_out;

    void* count_ptr = nullptr;
    cudaGetSymbolAddress(&count_ptr, g_count);
    cudaMemsetAsync(count_ptr, 0, N_NODES * sizeof(int));

    cudaFuncSetAttribute(k_gemm, cudaFuncAttributeMaxDynamicSharedMemorySize, SMEM_GEMM);

    k_init<<<(N_EDGES + 255) / 256, 256>>>(dst, edge_w, edge_b, attn);
    k_gemm<<<GEMM_BLOCKS, 256, SMEM_GEMM>>>(node_feats, node_w, node_b, attn);
    k_scan<<<1, 1024>>>();
    k_se<<<N_EDGES / 128, 256>>>(edge_feats, src, dst);
    k_gather<<<(N_NODES * 32 + 255) / 256, 256>>>(out);
}

// round 15
// speedup vs baseline: 1.1371x; 1.1268x over previous
#include <cuda_runtime.h>
#include <cuda_bf16.h>
#include <cstdint>
#include <cstddef>

#define N_NODES 40000
#define N_EDGES 640000
#define IN_F    256
#define EDGE_F  64
#define OUT_F   128
#define NH      8
#define DH      16
#define GEMM_BLOCKS 313

// ---------------- scratch ----------------
__device__ __align__(16) float g_Wh[(size_t)N_NODES * OUT_F];
__device__ __align__(16) float g_ssrc[N_NODES * NH];
__device__ __align__(16) float g_sdst[N_NODES * NH];
__device__ __align__(16) float g_sval[(size_t)N_EDGES * NH];   // CSR-ordered edge scores
__device__ __align__(16) int   g_ssidx[N_EDGES];               // CSR-ordered src ids
__device__ __align__(16) int   g_count[N_NODES];
__device__ __align__(16) int   g_rowstart[N_NODES + 1];
__device__ __align__(16) int   g_cursor[N_NODES];
__device__ float g_weff[NH * EDGE_F];
__device__ float g_beff[NH];

// ---------------- helpers ----------------
__device__ __forceinline__ uint32_t smem_u32(const void* p) {
    uint32_t a;
    asm("{ .reg .u64 t; cvta.to.shared.u64 t, %1; cvt.u32.u64 %0, t; }" : "=r"(a) : "l"(p));
    return a;
}
__device__ __forceinline__ uint32_t swz(uint32_t off) {
    return off ^ ((off >> 3) & 0x70);
}
__device__ __forceinline__ void ldsm4(uint32_t& r0, uint32_t& r1, uint32_t& r2, uint32_t& r3, uint32_t addr) {
    asm volatile("ldmatrix.sync.aligned.m8n8.x4.shared.b16 {%0,%1,%2,%3}, [%4];"
                 : "=r"(r0), "=r"(r1), "=r"(r2), "=r"(r3) : "r"(addr));
}
__device__ __forceinline__ void mma16816(float* c, uint32_t a0, uint32_t a1, uint32_t a2, uint32_t a3,
                                         uint32_t b0, uint32_t b1) {
    asm volatile("mma.sync.aligned.m16n8k16.row.col.f32.bf16.bf16.f32 "
                 "{%0,%1,%2,%3}, {%4,%5,%6,%7}, {%8,%9}, {%0,%1,%2,%3};"
                 : "+f"(c[0]), "+f"(c[1]), "+f"(c[2]), "+f"(c[3])
                 : "r"(a0), "r"(a1), "r"(a2), "r"(a3), "r"(b0), "r"(b1));
}
__device__ __forceinline__ uint32_t pack_bf16x2(float a, float b) {
    __nv_bfloat16 x = __float2bfloat16(a), y = __float2bfloat16(b);
    return (uint32_t)__bfloat16_as_ushort(x) | ((uint32_t)__bfloat16_as_ushort(y) << 16);
}

// ---------------- K0: dst histogram + fold attn into edge_w ----------------
__global__ void k_init(const int* __restrict__ dst,
                       const float* __restrict__ edge_w,
                       const float* __restrict__ edge_b,
                       const float* __restrict__ attn) {
    int e = blockIdx.x * blockDim.x + threadIdx.x;
    if (e < N_EDGES) atomicAdd(&g_count[dst[e]], 1);
    if (blockIdx.x == 0) {
        for (int i = threadIdx.x; i < NH * EDGE_F; i += blockDim.x) {
            int h = i >> 6, k = i & 63;
            float s = 0.f;
            #pragma unroll
            for (int d = 0; d < DH; d++)
                s += edge_w[(h * DH + d) * EDGE_F + k] * attn[h * 48 + 32 + d];
            g_weff[i] = s;
        }
        if (threadIdx.x < NH) {
            float s = 0.f;
            #pragma unroll
            for (int d = 0; d < DH; d++)
                s += edge_b[threadIdx.x * DH + d] * attn[threadIdx.x * 48 + 32 + d];
            g_beff[threadIdx.x] = s;
        }
    }
}

// ---------------- K1: bf16-split MMA GEMM, register-prefetch pipelined (R13-proven) ----------------
#define SMEM_GEMM 65536
__global__ __launch_bounds__(256) void k_gemm(const float* __restrict__ A,
                                              const float* __restrict__ B,
                                              const float* __restrict__ bias,
                                              const float* __restrict__ attn) {
    extern __shared__ char sm[];
    const uint32_t A_HI = 0, A_LO = 16384, B_HI = 32768, B_LO = 49152;
    uint32_t sbase = smem_u32(sm);

    int tid = threadIdx.x, w = tid >> 5, lane = tid & 31;
    int m0 = blockIdx.x * 128;
    int wm = (w >> 1) * 32, wn = (w & 1) * 64;
    int g = lane >> 2, t = lane & 3;

    int st_r[8], st_c[8];
    bool st_ok[8];
    #pragma unroll
    for (int i = 0; i < 8; i++) {
        int idx = tid + i * 256;
        st_r[i] = idx >> 4;
        st_c[i] = (idx & 15) << 2;
        st_ok[i] = (m0 + st_r[i]) < N_NODES;
    }

    float c[2][8][4];
    #pragma unroll
    for (int mt = 0; mt < 2; mt++)
        #pragma unroll
        for (int nt = 0; nt < 8; nt++)
            #pragma unroll
            for (int j = 0; j < 4; j++) c[mt][nt][j] = 0.f;

    float4 va[8], vb[8];
    #pragma unroll
    for (int i = 0; i < 8; i++) {
        va[i] = st_ok[i] ? *(const float4*)&A[(size_t)(m0 + st_r[i]) * IN_F + st_c[i]]
                         : make_float4(0.f, 0.f, 0.f, 0.f);
        vb[i] = *(const float4*)&B[(size_t)st_r[i] * IN_F + st_c[i]];
    }

    #pragma unroll 1
    for (int chunk = 0; chunk < 4; chunk++) {
        #pragma unroll
        for (int i = 0; i < 8; i++) {
            uint32_t o = swz((uint32_t)(st_r[i] * 128 + st_c[i] * 2));
            float4 vA = va[i], vB = vb[i];
            {
                float h0 = __bfloat162float(__float2bfloat16(vA.x));
                float h1 = __bfloat162float(__float2bfloat16(vA.y));
                float h2 = __bfloat162float(__float2bfloat16(vA.z));
                float h3 = __bfloat162float(__float2bfloat16(vA.w));
                *(uint2*)(sm + A_HI + o) = make_uint2(pack_bf16x2(h0, h1), pack_bf16x2(h2, h3));
                *(uint2*)(sm + A_LO + o) = make_uint2(pack_bf16x2(vA.x - h0, vA.y - h1),
                                                      pack_bf16x2(vA.z - h2, vA.w - h3));
            }
            {
                float h0 = __bfloat162float(__float2bfloat16(vB.x));
                float h1 = __bfloat162float(__float2bfloat16(vB.y));
                float h2 = __bfloat162float(__float2bfloat16(vB.z));
                float h3 = __bfloat162float(__float2bfloat16(vB.w));
                *(uint2*)(sm + B_HI + o) = make_uint2(pack_bf16x2(h0, h1), pack_bf16x2(h2, h3));
                *(uint2*)(sm + B_LO + o) = make_uint2(pack_bf16x2(vB.x - h0, vB.y - h1),
                                                      pack_bf16x2(vB.z - h2, vB.w - h3));
            }
        }
        __syncthreads();

        if (chunk < 3) {
            int k0n = (chunk + 1) << 6;
            #pragma unroll
            for (int i = 0; i < 8; i++) {
                va[i] = st_ok[i] ? *(const float4*)&A[(size_t)(m0 + st_r[i]) * IN_F + k0n + st_c[i]]
                                 : make_float4(0.f, 0.f, 0.f, 0.f);
                vb[i] = *(const float4*)&B[(size_t)st_r[i] * IN_F + k0n + st_c[i]];
            }
        }

        int lr = lane & 15, lc = (lane >> 4) << 3;
        #pragma unroll
        for (int ks = 0; ks < 4; ks++) {
            int kk = (ks << 4) + lc;
            uint32_t ao0 = swz((uint32_t)((wm + lr) * 128 + kk * 2));
            uint32_t ao1 = swz((uint32_t)((wm + 16 + lr) * 128 + kk * 2));
            uint32_t ah[2][4], al[2][4];
            ldsm4(ah[0][0], ah[0][1], ah[0][2], ah[0][3], sbase + A_HI + ao0);
            ldsm4(ah[1][0], ah[1][1], ah[1][2], ah[1][3], sbase + A_HI + ao1);
            ldsm4(al[0][0], al[0][1], al[0][2], al[0][3], sbase + A_LO + ao0);
            ldsm4(al[1][0], al[1][1], al[1][2], al[1][3], sbase + A_LO + ao1);
            #pragma unroll
            for (int np = 0; np < 4; np++) {
                uint32_t bo = swz((uint32_t)((wn + np * 16 + lr) * 128 + kk * 2));
                uint32_t bh[4], bl[4];
                ldsm4(bh[0], bh[1], bh[2], bh[3], sbase + B_HI + bo);
                ldsm4(bl[0], bl[1], bl[2], bl[3], sbase + B_LO + bo);
                #pragma unroll
                for (int mt = 0; mt < 2; mt++) {
                    mma16816(c[mt][np * 2],     ah[mt][0], ah[mt][1], ah[mt][2], ah[mt][3], bh[0], bh[2]);
                    mma16816(c[mt][np * 2],     ah[mt][0], ah[mt][1], ah[mt][2], ah[mt][3], bl[0], bl[2]);
                    mma16816(c[mt][np * 2],     al[mt][0], al[mt][1], al[mt][2], al[mt][3], bh[0], bh[2]);
                    mma16816(c[mt][np * 2 + 1], ah[mt][0], ah[mt][1], ah[mt][2], ah[mt][3], bh[1], bh[3]);
                    mma16816(c[mt][np * 2 + 1], ah[mt][0], ah[mt][1], ah[mt][2], ah[mt][3], bl[1], bl[3]);
                    mma16816(c[mt][np * 2 + 1], al[mt][0], al[mt][1], al[mt][2], al[mt][3], bh[1], bh[3]);
                }
            }
        }
        __syncthreads();
    }

    // ---- epilogue ----
    float as0[8], as1[8], ad0[8], ad1[8], bb0[8], bb1[8];
    #pragma unroll
    for (int nt = 0; nt < 8; nt++) {
        int col = wn + nt * 8 + t * 2;
        int h = col >> 4, d = col & 15;
        as0[nt] = attn[h * 48 + d];      as1[nt] = attn[h * 48 + d + 1];
        ad0[nt] = attn[h * 48 + 16 + d]; ad1[nt] = attn[h * 48 + 16 + d + 1];
        bb0[nt] = bias[col];             bb1[nt] = bias[col + 1];
    }
    float ps[2][2][4], pd[2][2][4];
    #pragma unroll
    for (int mt = 0; mt < 2; mt++)
        #pragma unroll
        for (int hf = 0; hf < 2; hf++)
            #pragma unroll
            for (int hh = 0; hh < 4; hh++) { ps[mt][hf][hh] = 0.f; pd[mt][hf][hh] = 0.f; }

    #pragma unroll
    for (int mt = 0; mt < 2; mt++) {
        #pragma unroll
        for (int hf = 0; hf < 2; hf++) {
            int m = m0 + wm + mt * 16 + g + hf * 8;
            bool ok = (m < N_NODES);
            #pragma unroll
            for (int nt = 0; nt < 8; nt++) {
                float v0 = c[mt][nt][hf * 2 + 0] + bb0[nt];
                float v1 = c[mt][nt][hf * 2 + 1] + bb1[nt];
                if (ok) {
                    int col = wn + nt * 8 + t * 2;
                    *(float2*)&g_Wh[(size_t)m * OUT_F + col] = make_float2(v0, v1);
                }
                ps[mt][hf][nt >> 1] += v0 * as0[nt] + v1 * as1[nt];
                pd[mt][hf][nt >> 1] += v0 * ad0[nt] + v1 * ad1[nt];
            }
        }
    }
    #pragma unroll
    for (int mt = 0; mt < 2; mt++)
        #pragma unroll
        for (int hf = 0; hf < 2; hf++)
            #pragma unroll
            for (int hh = 0; hh < 4; hh++) {
                float s = ps[mt][hf][hh], d2 = pd[mt][hf][hh];
                s += __shfl_xor_sync(0xffffffffu, s, 1);
                s += __shfl_xor_sync(0xffffffffu, s, 2);
                d2 += __shfl_xor_sync(0xffffffffu, d2, 1);
                d2 += __shfl_xor_sync(0xffffffffu, d2, 2);
                if (t == 0) {
                    int m = m0 + wm + mt * 16 + g + hf * 8;
                    if (m < N_NODES) {
                        int h = (w & 1) * 4 + hh;
                        g_ssrc[m * NH + h] = s;
                        g_sdst[m * NH + h] = d2;
                    }
                }
            }
}

// ---------------- K2: single-phase exclusive scan ----------------
__global__ __launch_bounds__(1024) void k_scan() {
    __shared__ int wsum[32];
    int tid = threadIdx.x, lane = tid & 31, wid = tid >> 5;
    int base = tid * 40;
    int4 v[10];
    #pragma unroll
    for (int j = 0; j < 10; j++) {
        int o = base + j * 4;
        v[j] = (o < N_NODES) ? *(const int4*)&g_count[o] : make_int4(0, 0, 0, 0);
    }
    int t = 0;
    #pragma unroll
    for (int j = 0; j < 10; j++) t += v[j].x + v[j].y + v[j].z + v[j].w;
    int x = t;
    #pragma unroll
    for (int o = 1; o < 32; o <<= 1) {
        int y = __shfl_up_sync(0xffffffffu, x, o);
        if (lane >= o) x += y;
    }
    if (lane == 31) wsum[wid] = x;
    __syncthreads();
    if (wid == 0) {
        int wv = wsum[lane], xx = wv;
        #pragma unroll
        for (int o = 1; o < 32; o <<= 1) {
            int y = __shfl_up_sync(0xffffffffu, xx, o);
            if (lane >= o) xx += y;
        }
        wsum[lane] = xx - wv;
    }
    __syncthreads();
    int run = (x - t) + wsum[wid];
    #pragma unroll
    for (int j = 0; j < 10; j++) {
        int o = base + j * 4;
        int4 r;
        r.x = run; run += v[j].x;
        r.y = run; run += v[j].y;
        r.z = run; run += v[j].z;
        r.w = run; run += v[j].w;
        if (o < N_NODES) {
            *(int4*)&g_rowstart[o] = r;
            *(int4*)&g_cursor[o]   = r;
        }
    }
    if (tid == 1023) g_rowstart[N_NODES] = run;
}

// ---------------- K3: s_e via tensor-core MMA (128-edge tile, exact R10 version) ----------------
__global__ __launch_bounds__(256) void k_se(const float* __restrict__ EF,
                                            const int* __restrict__ src,
                                            const int* __restrict__ dst) {
    __shared__ __align__(128) char sA_hi[128 * 128];
    __shared__ __align__(128) char sA_lo[128 * 128];
    __shared__ __align__(128) char sB_hi[8 * 128];
    __shared__ __align__(128) char sB_lo[8 * 128];
    __shared__ float sOut[128 * 8];
    __shared__ float sb[NH];

    int tid = threadIdx.x, w = tid >> 5, lane = tid & 31;
    int e0 = blockIdx.x * 128;

    #pragma unroll
    for (int i = 0; i < 8; i++) {
        int idx = tid + i * 256;
        int r = idx >> 4;
        int cc = (idx & 15) << 2;
        float4 v = *(const float4*)&EF[(size_t)(e0 + r) * EDGE_F + cc];
        uint32_t o = swz((uint32_t)(r * 128 + cc * 2));
        float h0 = __bfloat162float(__float2bfloat16(v.x));
        float h1 = __bfloat162float(__float2bfloat16(v.y));
        float h2 = __bfloat162float(__float2bfloat16(v.z));
        float h3 = __bfloat162float(__float2bfloat16(v.w));
        *(uint2*)(sA_hi + o) = make_uint2(pack_bf16x2(h0, h1), pack_bf16x2(h2, h3));
        *(uint2*)(sA_lo + o) = make_uint2(pack_bf16x2(v.x - h0, v.y - h1),
                                          pack_bf16x2(v.z - h2, v.w - h3));
    }
    if (tid < 128) {
        int h = tid >> 4, kq = (tid & 15) << 2;
        float4 v = *(const float4*)&g_weff[h * EDGE_F + kq];
        uint32_t o = swz((uint32_t)(h * 128 + kq * 2));
        float h0 = __bfloat162float(__float2bfloat16(v.x));
        float h1 = __bfloat162float(__float2bfloat16(v.y));
        float h2 = __bfloat162float(__float2bfloat16(v.z));
        float h3 = __bfloat162float(__float2bfloat16(v.w));
        *(uint2*)(sB_hi + o) = make_uint2(pack_bf16x2(h0, h1), pack_bf16x2(h2, h3));
        *(uint2*)(sB_lo + o) = make_uint2(pack_bf16x2(v.x - h0, v.y - h1),
                                          pack_bf16x2(v.z - h2, v.w - h3));
    }
    if (tid < NH) sb[tid] = g_beff[tid];
    __syncthreads();

    // MMA: each warp owns 16 edges, all 8 heads
    {
        uint32_t a_hi = smem_u32(sA_hi), a_lo = smem_u32(sA_lo);
        uint32_t b_hi = smem_u32(sB_hi), b_lo = smem_u32(sB_lo);
        int lr = lane & 15, lc = (lane >> 4) << 3;
        int br = lane & 7;
        float c[4] = {0.f, 0.f, 0.f, 0.f};
        #pragma unroll
        for (int kc = 0; kc < 4; kc++) {
            int kk = (kc << 4) + lc;
            uint32_t ao = swz((uint32_t)((w * 16 + lr) * 128 + kk * 2));
            uint32_t bo = swz((uint32_t)(br * 128 + kk * 2));
            uint32_t ah[4], al[4], bh[4], bl[4];
            ldsm4(ah[0], ah[1], ah[2], ah[3], a_hi + ao);
            ldsm4(al[0], al[1], al[2], al[3], a_lo + ao);
            ldsm4(bh[0], bh[1], bh[2], bh[3], b_hi + bo);
            ldsm4(bl[0], bl[1], bl[2], bl[3], b_lo + bo);
            mma16816(c, ah[0], ah[1], ah[2], ah[3], bh[0], bh[2]);
            mma16816(c, ah[0], ah[1], ah[2], ah[3], bl[0], bl[2]);
            mma16816(c, al[0], al[1], al[2], al[3], bh[0], bh[2]);
        }
        int g = lane >> 2, t = lane & 3;
        *(float2*)&sOut[(w * 16 + g) * 8 + t * 2]     = make_float2(c[0], c[1]);
        *(float2*)&sOut[(w * 16 + g + 8) * 8 + t * 2] = make_float2(c[2], c[3]);
    }
    __syncthreads();

    // scatter: one thread per edge (tid < 128) — single phase, no extra barrier
    if (tid < 128) {
        int e = e0 + tid;
        int s = src[e], d = dst[e];
        float4 o0 = *(float4*)&sOut[tid * 8];
        float4 o1 = *(float4*)&sOut[tid * 8 + 4];
        float4 r0 = *(const float4*)&g_ssrc[s * NH];
        float4 r1 = *(const float4*)&g_ssrc[s * NH + 4];
        int pos = atomicAdd(&g_cursor[d], 1);
        *(float4*)&g_sval[(size_t)pos * NH] =
            make_float4(o0.x + sb[0] + r0.x, o0.y + sb[1] + r0.y,
                        o0.z + sb[2] + r0.z, o0.w + sb[3] + r0.w);
        *(float4*)&g_sval[(size_t)pos * NH + 4] =
            make_float4(o1.x + sb[4] + r1.x, o1.y + sb[5] + r1.y,
                        o1.z + sb[6] + r1.z, o1.w + sb[7] + r1.w);
        g_ssidx[pos] = s;
    }
}

// ---------------- K4: gather per node (warp/node), unrolled x4 ----------------
__global__ __launch_bounds__(256) void k_gather(float* __restrict__ out) {
    int warp = (blockIdx.x * blockDim.x + threadIdx.x) >> 5;
    int lane = threadIdx.x & 31;
    if (warp >= N_NODES) return;
    int h = lane >> 2;
    float sd = g_sdst[warp * NH + h];
    int beg = g_rowstart[warp], end = g_rowstart[warp + 1];
    float4 acc = make_float4(0.f, 0.f, 0.f, 0.f);
    float z = 0.f;
    int i = beg;
    for (; i + 4 <= end; i += 4) {
        int s0 = g_ssidx[i],     s1 = g_ssidx[i + 1];
        int s2 = g_ssidx[i + 2], s3 = g_ssidx[i + 3];
        float a0 = g_sval[(size_t)i * NH + h];
        float a1 = g_sval[(size_t)(i + 1) * NH + h];
        float a2 = g_sval[(size_t)(i + 2) * NH + h];
        float a3 = g_sval[(size_t)(i + 3) * NH + h];
        float4 w0 = *(const float4*)&g_Wh[(size_t)s0 * OUT_F + lane * 4];
        float4 w1 = *(const float4*)&g_Wh[(size_t)s1 * OUT_F + lane * 4];
        float4 w2 = *(const float4*)&g_Wh[(size_t)s2 * OUT_F + lane * 4];
        float4 w3 = *(const float4*)&g_Wh[(size_t)s3 * OUT_F + lane * 4];
        float e0 = a0 + sd; e0 = fmaxf(e0, 0.2f * e0);
        float e1 = a1 + sd; e1 = fmaxf(e1, 0.2f * e1);
        float e2 = a2 + sd; e2 = fmaxf(e2, 0.2f * e2);
        float e3 = a3 + sd; e3 = fmaxf(e3, 0.2f * e3);
        float x0 = __expf(e0), x1 = __expf(e1), x2 = __expf(e2), x3 = __expf(e3);
        z += (x0 + x1) + (x2 + x3);
        acc.x += x0 * w0.x + x1 * w1.x + x2 * w2.x + x3 * w3.x;
        acc.y += x0 * w0.y + x1 * w1.y + x2 * w2.y + x3 * w3.y;
        acc.z += x0 * w0.z + x1 * w1.z + x2 * w2.z + x3 * w3.z;
        acc.w += x0 * w0.w + x1 * w1.w + x2 * w2.w + x3 * w3.w;
    }
    for (; i < end; i++) {
        int s0 = g_ssidx[i];
        float a0 = g_sval[(size_t)i * NH + h];
        float4 w0 = *(const float4*)&g_Wh[(size_t)s0 * OUT_F + lane * 4];
        float e0 = a0 + sd; e0 = fmaxf(e0, 0.2f * e0);
        float x0 = __expf(e0);
        z += x0;
        acc.x += x0 * w0.x; acc.y += x0 * w0.y;
        acc.z += x0 * w0.z; acc.w += x0 * w0.w;
    }
    float4 o = make_float4(0.f, 0.f, 0.f, 0.f);
    if (end > beg) {
        float inv = 1.f / z;
        o = make_float4(acc.x * inv, acc.y * inv, acc.z * inv, acc.w * inv);
    }
    *(float4*)&out[(size_t)warp * OUT_F + lane * 4] = o;
}

// ---------------- launch ----------------
extern "C" void kernel_launch(void* const* d_in, const int* in_sizes, int n_in,
                              void* d_out, int out_size) {
    const float* node_feats = (const float*)d_in[0];
    const float* edge_feats = (const float*)d_in[1];
    const int*   src        = (const int*)d_in[2];
    const int*   dst        = (const int*)d_in[3];
    const float* node_w     = (const float*)d_in[4];
    const float* node_b     = (const float*)d_in[5];
    const float* edge_w     = (const float*)d_in[6];
    const float* edge_b     = (const float*)d_in[7];
    const float* attn       = (const float*)d_in[8];
    float* out = (float*)d_out;

    void* count_ptr = nullptr;
    cudaGetSymbolAddress(&count_ptr, g_count);
    cudaMemsetAsync(count_ptr, 0, N_NODES * sizeof(int));

    cudaFuncSetAttribute(k_gemm, cudaFuncAttributeMaxDynamicSharedMemorySize, SMEM_GEMM);

    k_init<<<(N_EDGES + 255) / 256, 256>>>(dst, edge_w, edge_b, attn);
    k_gemm<<<GEMM_BLOCKS, 256, SMEM_GEMM>>>(node_feats, node_w, node_b, attn);
    k_scan<<<1, 1024>>>();
    k_se<<<N_EDGES / 128, 256>>>(edge_feats, src, dst);
    k_gather<<<(N_NODES * 32 + 255) / 256, 256>>>(out);
}